// round 16
// baseline (speedup 1.0000x reference)
#include <cuda_runtime.h>

#define SIZE 512
#define NS 256
#define NT 128
#define KST4 130               // per-warp keep stride in float4 (260 float2)
#define KSCALE 369.3298503f    // 256 * log2(e)

__device__ __forceinline__ float fsqrt_approx(float x) {
    float r; asm("sqrt.approx.f32 %0, %1;" : "=f"(r) : "f"(x)); return r;
}
__device__ __forceinline__ float fexp2_approx(float x) {
    float r; asm("ex2.approx.f32 %0, %1;" : "=f"(r) : "f"(x)); return r;
}
__device__ __forceinline__ float flog2_approx(float x) {
    float r; asm("lg2.approx.f32 %0, %1;" : "=f"(r) : "f"(x)); return r;
}
__device__ __forceinline__ float frcp_approx(float x) {
    float r; asm("rcp.approx.f32 %0, %1;" : "=f"(r) : "f"(x)); return r;
}

// ---- fused kernel: 4 independent warps/CTA, one 8x8 tile per warp, 2 px/lane ----
__global__ __launch_bounds__(NT)
void glyph_kernel(const float* __restrict__ cp, float* __restrict__ out)
{
    __shared__ float4 samp[NS / 2];          // 256 K-scaled samples
    __shared__ float4 keepbuf[4 * KST4];     // private AoS segment per warp

    const int tid  = threadIdx.x;
    const int lane = tid & 31;
    const int w    = tid >> 5;

    // ---- per-CTA K-scaled Bezier samples: thread t computes samples 2t, 2t+1 ----
    {
        const float4* cp4 = (const float4*)cp;
        const int stroke = tid >> 4;
        const float4 a = cp4[2 * stroke];
        const float4 b = cp4[2 * stroke + 1];
        const float q0x = __saturatef(a.x), q0y = __saturatef(a.y);
        const float q1x = __saturatef(a.z), q1y = __saturatef(a.w);
        const float q2x = __saturatef(b.x), q2y = __saturatef(b.y);
        const float q3x = __saturatef(b.z), q3y = __saturatef(b.w);
        const int j = (2 * tid) & 31;
        float4 o;
        {
            const float t  = (float)j * (1.0f / 31.0f);
            const float mt = 1.0f - t;
            const float w0 = mt * mt * mt, w1 = 3.0f * mt * mt * t;
            const float w2 = 3.0f * mt * t * t, w3 = t * t * t;
            o.x = (w0 * q0x + w1 * q1x + w2 * q2x + w3 * q3x) * KSCALE;
            o.y = (w0 * q0y + w1 * q1y + w2 * q2y + w3 * q3y) * KSCALE;
        }
        {
            const float t  = (float)(j + 1) * (1.0f / 31.0f);
            const float mt = 1.0f - t;
            const float w0 = mt * mt * mt, w1 = 3.0f * mt * mt * t;
            const float w2 = 3.0f * mt * t * t, w3 = t * t * t;
            o.z = (w0 * q0x + w1 * q1x + w2 * q2x + w3 * q3x) * KSCALE;
            o.w = (w0 * q0y + w1 * q1y + w2 * q2y + w3 * q3y) * KSCALE;
        }
        samp[tid] = o;
    }
    __syncthreads();
    // warps fully independent from here

    const int tile = blockIdx.x * 4 + w;     // 0..4095
    const int x0 = (tile & 63) * 8;          // 64 x 64 tiles of 8x8 px
    const int y0 = (tile >> 6) * 8;

    const float inv = 1.0f / 511.0f;
    const float cxs = ((float)x0 + 3.5f) * inv * KSCALE;
    const float cys = ((float)y0 + 3.5f) * inv * KSCALE;
    const float R  = 0.0096875f + 1e-4f;     // 0.5*sqrt(7^2+7^2)/511

    // ---- 8 samples per lane: scaled center dist^2 + warp-min ----
    float2 s[8];
    float  dc2[8];
    float  m = 1e30f;
    #pragma unroll
    for (int j = 0; j < 4; j++) {
        const float4 v = samp[j * 32 + lane];
        s[2 * j]     = make_float2(v.x, v.y);
        s[2 * j + 1] = make_float2(v.z, v.w);
        float ax = cxs - v.x, ay = cys - v.y;
        dc2[2 * j] = fmaf(ax, ax, ay * ay);
        ax = cxs - v.z; ay = cys - v.w;
        dc2[2 * j + 1] = fmaf(ax, ax, ay * ay);
        m = fminf(m, fminf(dc2[2 * j], dc2[2 * j + 1]));
    }
    const float dcmin_s =
        sqrtf(__int_as_float(__reduce_min_sync(0xffffffffu, __float_as_int(m))));

    // two pixels per lane: (px, py) and (px, py+4)
    const int px = x0 + (lane & 7);
    const int py = y0 + (lane >> 3);
    const int p1 = py * SIZE + px;
    const int p2 = p1 + 4 * SIZE;

    // ---- tile skip: coverage < 1.6e-4 ----
    if (dcmin_s > 0.1154f * KSCALE) {
        out[p1] = 1.0f;
        out[p2] = 1.0f;
        return;
    }

    // ---- warp compaction: keep dc_s <= dcmin_s + (2R + 0.055)*K ----
    const float thr  = dcmin_s + (2.0f * R + 0.055f) * KSCALE;
    const float thr2 = thr * thr;
    float2* kp = (float2*)(keepbuf + w * KST4);
    const unsigned lt = (1u << lane) - 1u;
    int c = 0;
    #pragma unroll
    for (int j = 0; j < 8; j++) {
        const bool k = (dc2[j] <= thr2);
        const unsigned msk = __ballot_sync(0xffffffffu, k);
        if (k) kp[c + __popc(msk & lt)] = s[j];
        c += __popc(msk);
    }
    if (lane < 4) kp[c + lane] = make_float2(cxs + 1000.0f, cys);  // sentinels: ex2(-1000)=0
    __syncwarp();
    const int nIt = ((c + 3) & ~3) >> 1;     // float4 iterations (even count)

    // ---- 2-pixel single-pass soft-min: ax^2 shared across the pixel pair ----
    const float gxs  = (float)px * inv * KSCALE;
    const float gy1s = (float)py * inv * KSCALE;
    const float DYS  = 4.0f * inv * KSCALE;  // scaled y-offset of second pixel
    const float4* kp4 = (const float4*)kp;
    float a1A = 0.0f, a1B = 0.0f, a2A = 0.0f, a2B = 0.0f;  // 4 independent chains
    #pragma unroll 4
    for (int i = 0; i < nIt; i++) {
        const float4 q = kp4[i];             // broadcast LDS.128, 2 samples
        // sample (q.x, q.y)
        float ax  = gxs - q.x;
        float axx = ax * ax;
        float ay  = gy1s - q.y;
        float ay2 = ay + DYS;
        const float dA1 = fsqrt_approx(fmaf(ay,  ay,  axx));
        const float dA2 = fsqrt_approx(fmaf(ay2, ay2, axx));
        // sample (q.z, q.w)
        float bx  = gxs - q.z;
        float bxx = bx * bx;
        float by  = gy1s - q.w;
        float by2 = by + DYS;
        const float dB1 = fsqrt_approx(fmaf(by,  by,  bxx));
        const float dB2 = fsqrt_approx(fmaf(by2, by2, bxx));
        a1A += fexp2_approx(-dA1);
        a2A += fexp2_approx(-dA2);
        a1B += fexp2_approx(-dB1);
        a2B += fexp2_approx(-dB2);
    }

    const float C1 = -0.69314718f / 256.0f;
    const float C2 = 200.0f * 1.44269504f;
    const float md1 = flog2_approx(a1A + a1B) * C1;
    const float md2 = flog2_approx(a2A + a2B) * C1;
    out[p1] = frcp_approx(1.0f + fexp2_approx((0.04f - md1) * C2));
    out[p2] = frcp_approx(1.0f + fexp2_approx((0.04f - md2) * C2));
}

extern "C" void kernel_launch(void* const* d_in, const int* in_sizes, int n_in,
                              void* d_out, int out_size) {
    const float* cp = (const float*)d_in[0];   // control_points [8,4,2]
    float* out = (float*)d_out;
    glyph_kernel<<<1024, NT>>>(cp, out);       // 1024 CTAs x 4 warp-tiles = 4096 tiles
}